// round 16
// baseline (speedup 1.0000x reference)
#include <cuda_runtime.h>
#include <cuda_fp16.h>
#include <mma.h>
#include <cstdint>

using namespace nvcuda;

#define N_   4
#define C_   128
#define D_   16
#define H_   64
#define W_   64
#define L_   512
#define TAPS 27
#define PD   18
#define PH   66
#define PW   66
#define LDT  72           // row pitch in halfs: 144B, LDSM conflict-free
#define NSUB 54           // 18 X-stages x 3 kw substages
#define XW_ROWS 132       // 2 input h-rows x 66 wpad

// ---------------------------------------------------------------------------
// Device-global scratch (allocation-free rule). .bss zero-init; g_xT pad
// borders never written -> stay zero across graph replays.
// ---------------------------------------------------------------------------
__device__ float  g_style[N_ * C_];                                    // [n][i]
__device__ __align__(16) __half g_wmod[(size_t)N_ * TAPS * C_ * C_];   // [n][t][o][i]
__device__ __align__(16) __half g_xT[(size_t)N_ * PD * PH * PW * C_];  // padded ch-last

// ---------------------------------------------------------------------------
// cp.async helpers (baseline PTX)
// ---------------------------------------------------------------------------
__device__ __forceinline__ uint32_t smem_u32(const void* p) {
    uint32_t a;
    asm("{ .reg .u64 t; cvta.to.shared.u64 t, %1; cvt.u32.u64 %0, t; }" : "=r"(a) : "l"(p));
    return a;
}
__device__ __forceinline__ void cp_async16(uint32_t dst, const void* src) {
    asm volatile("cp.async.cg.shared.global [%0], [%1], 16;" :: "r"(dst), "l"(src));
}
#define CP_COMMIT()  asm volatile("cp.async.commit_group;" ::: "memory")
#define CP_WAIT(n)   asm volatile("cp.async.wait_group %0;" :: "n"(n) : "memory")

// ---------------------------------------------------------------------------
// Kernel 1: style[n][i] = latent[n] . fc_w[i] + fc_b[i]   (warp per i)
// ---------------------------------------------------------------------------
__global__ void style_kernel(const float* __restrict__ latent,
                             const float* __restrict__ fc_w,
                             const float* __restrict__ fc_b) {
    const int n = blockIdx.y;
    const int wid = threadIdx.x >> 5, lid = threadIdx.x & 31;
    const int i = blockIdx.x * 4 + wid;
    const float* lat  = latent + n * L_;
    const float* wrow = fc_w + (size_t)i * L_;
    float acc = 0.f;
#pragma unroll 4
    for (int l = lid; l < L_; l += 32) acc = fmaf(lat[l], wrow[l], acc);
#pragma unroll
    for (int o = 16; o > 0; o >>= 1) acc += __shfl_xor_sync(0xFFFFFFFFu, acc, o);
    if (lid == 0) g_style[n * C_ + i] = acc + fc_b[i];
}

// ---------------------------------------------------------------------------
// Kernel 2: modulate + demodulate -> fp16, layout [n][t][o][i].
// One CTA per o; weight[o] row loaded ONCE into registers, looped over n.
// ---------------------------------------------------------------------------
__global__ void modw_kernel(const float* __restrict__ weight) {
    const int o = blockIdx.x, i = threadIdx.x;
    const float* wp = weight + (o * C_ + i) * TAPS;
    float w[TAPS];
#pragma unroll
    for (int t = 0; t < TAPS; ++t) w[t] = wp[t];

    __shared__ float red[C_];
    for (int n = 0; n < N_; ++n) {
        float s = g_style[n * C_ + i];
        float ss = 0.f;
#pragma unroll
        for (int t = 0; t < TAPS; ++t) { float v = w[t] * s; ss = fmaf(v, v, ss); }
        red[i] = ss;
        __syncthreads();
#pragma unroll
        for (int st = 64; st > 0; st >>= 1) {
            if (i < st) red[i] += red[i + st];
            __syncthreads();
        }
        float r = rsqrtf(red[0] + 1e-8f) * s;
#pragma unroll
        for (int t = 0; t < TAPS; ++t)
            g_wmod[(((size_t)(n * TAPS + t) * C_) + o) * C_ + i] = __float2half_rn(w[t] * r);
        __syncthreads();   // red[] reuse across n
    }
}

// ---------------------------------------------------------------------------
// Kernel 3: transpose x -> padded channels-last fp16 xT[n][d+1][h+1][w+1][i]
// 512 threads, 2 h-rows per CTA, 64-channel phases (2 phases, 4 barriers).
// ---------------------------------------------------------------------------
__global__ __launch_bounds__(512)
void transpose_kernel(const float* __restrict__ x) {
    const int h0 = blockIdx.x * 2, d = blockIdx.y, n = blockIdx.z;
    const int tid = threadIdx.x;
    __shared__ float ts[2][64][65];
    for (int ic = 0; ic < 2; ++ic) {
        const int i0 = ic * 64;
        // load 2 h x 64 ch x 64 w, coalesced along w
#pragma unroll
        for (int r = 0; r < 16; ++r) {
            int e = tid + r * 512;              // 0..8191
            int hh = e >> 12;                   // 0..1
            int ii = (e >> 6) & 63, w = e & 63;
            ts[hh][ii][w] = x[((((size_t)n * C_ + i0 + ii) * D_ + d) * H_ + (h0 + hh)) * W_ + w];
        }
        __syncthreads();
        // write: thread -> (hh, w, two groups-of-8-i); 16B stores, i contiguous
        int hh = tid >> 8;                      // 0..1
        int w = (tid >> 2) & 63, g = tid & 3;
        __half* dst = g_xT + ((((size_t)n * PD + d + 1) * PH + (h0 + hh + 1)) * PW + (w + 1)) * C_ + i0;
#pragma unroll
        for (int gg = 0; gg < 2; ++gg) {
            int grp = g + gg * 4;               // 0..7 -> 8 groups of 8 channels
            __half hb[8];
#pragma unroll
            for (int j = 0; j < 8; ++j) hb[j] = __float2half_rn(ts[hh][grp * 8 + j][w]);
            *(uint4*)(dst + grp * 8) = *(const uint4*)hb;
        }
        __syncthreads();
    }
}

// ---------------------------------------------------------------------------
// Kernel 4 (R8/R15-proven): conv = 54 accumulated 128x128x64 HMMA sub-GEMMs.
// CTA = (n, d, h-pair), 8 warps x (64o x 32z), 2 CTAs/SM.
// X staged once per (kd,kh,ic) as 2x66 row window (kw-shift reuse);
// W per-tap in a 4-deep ring; one barrier + one cp.async group per substage,
// 3-group lead. Only change vs R15: /66,%66 -> compare-select (no new regs).
// ---------------------------------------------------------------------------
__global__ __launch_bounds__(256, 2)
void conv_kernel(float* __restrict__ out) {
    const int hb = blockIdx.x, d = blockIdx.y, n = blockIdx.z;
    const int h0 = hb * 2;
    const int tid = threadIdx.x, wid = tid >> 5;

    __shared__ __align__(16) __half XW[2][XW_ROWS * LDT];   // 2 x 19008 B
    __shared__ __align__(16) __half WS[4][128 * LDT];       // 4 x 18432 B

    const int wo = wid >> 2;        // 0..1 -> o block of 64
    const int wz = wid & 3;         // 0..3 -> z block of 32

    wmma::fragment<wmma::accumulator, 16, 16, 16, float> c[4][2];
#pragma unroll
    for (int m = 0; m < 4; ++m)
#pragma unroll
        for (int nn = 0; nn < 2; ++nn) wmma::fill_fragment(c[m][nn], 0.f);

    const __half* xT_n = g_xT + (size_t)n * PD * PH * PW * C_;
    const __half* wm_n = g_wmod + (size_t)n * TAPS * C_ * C_;

    // X window staging: xs = ic*9 + kd*3 + kh. 1056 16B chunks (132 rows x 8).
    // row < 66 -> hh=0; else hh=1 (covers the tid<32 tail rows 128..131 too).
    auto stageX = [&](int xs, int slot) {
        const int ic = xs / 9, rr = xs - ic * 9;
        const int kd = rr / 3, kh = rr - kd * 3;
        const __half* base = xT_n + (((size_t)(d + kd) * PH) + (h0 + kh)) * PW * C_ + ic * 64;
        const uint32_t dst = smem_u32(&XW[slot][0]);
#pragma unroll
        for (int it = 0; it < 4; ++it) {
            int cch = tid + it * 256;                 // 0..1023
            int row = cch >> 3, q = cch & 7;
            int hh = (row >= 66) ? 1 : 0;
            int ww = row - (hh ? 66 : 0);
            cp_async16(dst + (uint32_t)(row * LDT + q * 8) * 2,
                       base + ((size_t)hh * PW + ww) * C_ + q * 8);
        }
        if (tid < 32) {                               // chunks 1024..1055: rows 128..131
            int cch = 1024 + tid;
            int row = cch >> 3, q = cch & 7;
            int ww = row - 66;
            cp_async16(dst + (uint32_t)(row * LDT + q * 8) * 2,
                       base + ((size_t)1 * PW + ww) * C_ + q * 8);
        }
    };

    // W tile staging for substage u: t = (kd*3+kh)*3 + kw, i-chunk ic. 1024 chunks.
    auto stageW = [&](int u, int slot) {
        const int xs = u / 3, kw = u - xs * 3;
        const int ic = xs / 9, rr = xs - ic * 9;
        const int t = rr * 3 + kw;
        const __half* wb = wm_n + (size_t)t * C_ * C_ + ic * 64;
        const uint32_t dst = smem_u32(&WS[slot][0]);
#pragma unroll
        for (int it = 0; it < 4; ++it) {
            int cch = tid + it * 256;
            int row = cch >> 3, q = cch & 7;
            cp_async16(dst + (uint32_t)(row * LDT + q * 8) * 2,
                       wb + (size_t)row * C_ + q * 8);
        }
    };

    auto compute = [&](int kw, int xslot, int wslot) {
        const __half* Wbase = &WS[wslot][wo * 64 * LDT];
        const int z0 = wz * 32;
        const int hh0 = z0 >> 6, w00 = z0 & 63;
        const int z1 = z0 + 16;
        const int hh1 = z1 >> 6, w01 = z1 & 63;
        const __half* Xb0 = &XW[xslot][(hh0 * 66 + w00 + kw) * LDT];
        const __half* Xb1 = &XW[xslot][(hh1 * 66 + w01 + kw) * LDT];
#pragma unroll
        for (int k = 0; k < 4; ++k) {
            wmma::fragment<wmma::matrix_a, 16, 16, 16, __half, wmma::row_major> a[4];
            wmma::fragment<wmma::matrix_b, 16, 16, 16, __half, wmma::col_major> b[2];
            wmma::load_matrix_sync(b[0], Xb0 + k * 16, LDT);
            wmma::load_matrix_sync(b[1], Xb1 + k * 16, LDT);
#pragma unroll
            for (int m = 0; m < 4; ++m) {
                wmma::load_matrix_sync(a[m], Wbase + (m * 16) * LDT + k * 16, LDT);
#pragma unroll
                for (int nn = 0; nn < 2; ++nn)
                    wmma::mma_sync(c[m][nn], a[m], b[nn], c[m][nn]);
            }
        }
    };

    // Prologue: groups 0{X0,W0}, 1{W1}, 2{W2}. Substage u issues group u+3.
    stageX(0, 0); stageW(0, 0); CP_COMMIT();
    stageW(1, 1); CP_COMMIT();
    stageW(2, 2); CP_COMMIT();

    for (int u = 0; u < NSUB; ++u) {
        const int xs = u / 3, kw = u - xs * 3;
        if (u < NSUB - 3) CP_WAIT(2);
        else              CP_WAIT(0);
        __syncthreads();                 // data for substage u visible; old bufs free
        if (u + 3 < NSUB) {
            stageW(u + 3, (u + 3) & 3);
            if (kw == 0) stageX(xs + 1, (xs + 1) & 1);
            CP_COMMIT();
        }
        compute(kw, xs & 1, u & 3);
    }

    // Epilogue: 16x16 fragments straight to gmem (z tiles never straddle hh).
#pragma unroll
    for (int m = 0; m < 4; ++m) {
        const int o = wo * 64 + m * 16;
#pragma unroll
        for (int nn = 0; nn < 2; ++nn) {
            const int z = wz * 32 + nn * 16;
            const int hh = z >> 6, w0 = z & 63;
            float* dst = out + (((size_t)n * C_ + o) * D_ + d) * (H_ * W_) + (h0 + hh) * W_ + w0;
            wmma::store_matrix_sync(dst, c[m][nn], D_ * H_ * W_, wmma::mem_row_major);
        }
    }
}

// ---------------------------------------------------------------------------
extern "C" void kernel_launch(void* const* d_in, const int* in_sizes, int n_in,
                              void* d_out, int out_size) {
    const float* x      = (const float*)d_in[0];
    const float* latent = (const float*)d_in[1];
    const float* weight = (const float*)d_in[2];
    const float* fc_w   = (const float*)d_in[3];
    const float* fc_b   = (const float*)d_in[4];
    float* out = (float*)d_out;

    style_kernel<<<dim3(C_ / 4, N_), 128>>>(latent, fc_w, fc_b);
    modw_kernel<<<C_, C_>>>(weight);
    transpose_kernel<<<dim3(H_ / 2, D_, N_), 512>>>(x);
    conv_kernel<<<dim3(H_ / 2, D_, N_), 256>>>(out);
}

// round 17
// speedup vs baseline: 1.0064x; 1.0064x over previous
#include <cuda_runtime.h>
#include <cuda_fp16.h>
#include <mma.h>
#include <cstdint>

using namespace nvcuda;

#define N_   4
#define C_   128
#define D_   16
#define H_   64
#define W_   64
#define L_   512
#define TAPS 27
#define PD   18
#define PH   66
#define PW   66
#define LDT  72           // row pitch in halfs: 144B, LDSM conflict-free
#define NSUB 54           // 18 X-stages x 3 kw substages
#define XW_ROWS 132       // 2 input h-rows x 66 wpad
#define TBLOCKS 2048      // transpose blocks: (H/2)*D*N = 32*16*4

// ---------------------------------------------------------------------------
// Device-global scratch (allocation-free rule). .bss zero-init; g_xT pad
// borders never written -> stay zero across graph replays.
// ---------------------------------------------------------------------------
__device__ float  g_style[N_ * C_];                                    // [n][i]
__device__ __align__(16) __half g_wmod[(size_t)N_ * TAPS * C_ * C_];   // [n][t][o][i]
__device__ __align__(16) __half g_xT[(size_t)N_ * PD * PH * PW * C_];  // padded ch-last

// ---------------------------------------------------------------------------
// cp.async helpers (baseline PTX)
// ---------------------------------------------------------------------------
__device__ __forceinline__ uint32_t smem_u32(const void* p) {
    uint32_t a;
    asm("{ .reg .u64 t; cvta.to.shared.u64 t, %1; cvt.u32.u64 %0, t; }" : "=r"(a) : "l"(p));
    return a;
}
__device__ __forceinline__ void cp_async16(uint32_t dst, const void* src) {
    asm volatile("cp.async.cg.shared.global [%0], [%1], 16;" :: "r"(dst), "l"(src));
}
#define CP_COMMIT()  asm volatile("cp.async.commit_group;" ::: "memory")
#define CP_WAIT(n)   asm volatile("cp.async.wait_group %0;" :: "n"(n) : "memory")

// ---------------------------------------------------------------------------
// Kernel 1: style[n][i] = latent[n] . fc_w[i] + fc_b[i]   (warp per i)
// ---------------------------------------------------------------------------
__global__ void style_kernel(const float* __restrict__ latent,
                             const float* __restrict__ fc_w,
                             const float* __restrict__ fc_b) {
    const int n = blockIdx.y;
    const int wid = threadIdx.x >> 5, lid = threadIdx.x & 31;
    const int i = blockIdx.x * 4 + wid;
    const float* lat  = latent + n * L_;
    const float* wrow = fc_w + (size_t)i * L_;
    float acc = 0.f;
#pragma unroll 4
    for (int l = lid; l < L_; l += 32) acc = fmaf(lat[l], wrow[l], acc);
#pragma unroll
    for (int o = 16; o > 0; o >>= 1) acc += __shfl_xor_sync(0xFFFFFFFFu, acc, o);
    if (lid == 0) g_style[n * C_ + i] = acc + fc_b[i];
}

// ---------------------------------------------------------------------------
// Kernel 2 (fused): blocks [0,TBLOCKS) transpose x -> padded channels-last
// fp16 xT; blocks [TBLOCKS, TBLOCKS+128) do modulate+demodulate (modw).
// Both depend only on style/x, so they run in one launch; modw's ~4us hides
// under the transpose's HBM-bound tail. 512 threads; modw work is guarded to
// tid<128 but ALL threads join its barriers in identical sequence.
// ---------------------------------------------------------------------------
__global__ __launch_bounds__(512)
void prep_kernel(const float* __restrict__ x, const float* __restrict__ weight) {
    const int b = blockIdx.x;
    const int tid = threadIdx.x;

    if (b < TBLOCKS) {
        // ---- transpose: 2 h-rows per CTA, 32-channel phases (R15-proven) ----
        const int hb = b & 31, d = (b >> 5) & 15, n = b >> 9;
        const int h0 = hb * 2;
        __shared__ float ts[2][32][65];
        for (int ic = 0; ic < 4; ++ic) {
            const int i0 = ic * 32;
#pragma unroll
            for (int r = 0; r < 8; ++r) {
                int e = tid + r * 512;              // 0..4095
                int hh = e >> 11;                   // 0..1
                int ii = (e >> 6) & 31, w = e & 63;
                ts[hh][ii][w] = x[((((size_t)n * C_ + i0 + ii) * D_ + d) * H_ + (h0 + hh)) * W_ + w];
            }
            __syncthreads();
            int hh = tid >> 8;                      // 0..1
            int w = (tid >> 2) & 63, g = tid & 3;
            __half hb8[8];
#pragma unroll
            for (int j = 0; j < 8; ++j) hb8[j] = __float2half_rn(ts[hh][g * 8 + j][w]);
            __half* dst = g_xT + ((((size_t)n * PD + d + 1) * PH + (h0 + hh + 1)) * PW + (w + 1)) * C_ + i0 + g * 8;
            *(uint4*)dst = *(const uint4*)hb8;
            __syncthreads();
        }
    } else {
        // ---- modw: one CTA per o; weight[o] row loaded once, looped over n ----
        const int o = b - TBLOCKS;
        const int i = tid & 127;
        const bool active = (tid < 128);
        float w[TAPS];
        if (active) {
            const float* wp = weight + (o * C_ + i) * TAPS;
#pragma unroll
            for (int t = 0; t < TAPS; ++t) w[t] = wp[t];
        }
        __shared__ float red[C_];
        for (int n = 0; n < N_; ++n) {
            float s = 0.f, ss = 0.f;
            if (active) {
                s = g_style[n * C_ + i];
#pragma unroll
                for (int t = 0; t < TAPS; ++t) { float v = w[t] * s; ss = fmaf(v, v, ss); }
                red[i] = ss;
            }
            __syncthreads();
#pragma unroll
            for (int st = 64; st > 0; st >>= 1) {
                if (active && i < st) red[i] += red[i + st];
                __syncthreads();
            }
            if (active) {
                float r = rsqrtf(red[0] + 1e-8f) * s;
#pragma unroll
                for (int t = 0; t < TAPS; ++t)
                    g_wmod[(((size_t)(n * TAPS + t) * C_) + o) * C_ + i] = __float2half_rn(w[t] * r);
            }
            __syncthreads();   // red[] reuse across n
        }
    }
}

// ---------------------------------------------------------------------------
// Kernel 3 (R15-proven, verbatim): conv = 54 accumulated 128x128x64 HMMA
// sub-GEMMs. CTA = (n, d, h-pair), 8 warps x (64o x 32z), 2 CTAs/SM.
// X staged once per (kd,kh,ic) as 2x66 row window (kw-shift reuse);
// W per-tap in a 4-deep ring; one barrier + one cp.async group per substage,
// 3-group lead.
// ---------------------------------------------------------------------------
__global__ __launch_bounds__(256, 2)
void conv_kernel(float* __restrict__ out) {
    const int hb = blockIdx.x, d = blockIdx.y, n = blockIdx.z;
    const int h0 = hb * 2;
    const int tid = threadIdx.x, wid = tid >> 5;

    __shared__ __align__(16) __half XW[2][XW_ROWS * LDT];   // 2 x 19008 B
    __shared__ __align__(16) __half WS[4][128 * LDT];       // 4 x 18432 B

    const int wo = wid >> 2;        // 0..1 -> o block of 64
    const int wz = wid & 3;         // 0..3 -> z block of 32

    wmma::fragment<wmma::accumulator, 16, 16, 16, float> c[4][2];
#pragma unroll
    for (int m = 0; m < 4; ++m)
#pragma unroll
        for (int nn = 0; nn < 2; ++nn) wmma::fill_fragment(c[m][nn], 0.f);

    const __half* xT_n = g_xT + (size_t)n * PD * PH * PW * C_;
    const __half* wm_n = g_wmod + (size_t)n * TAPS * C_ * C_;

    // X window staging: xs = ic*9 + kd*3 + kh. 1056 16B chunks (2 rows x 66 x 8).
    auto stageX = [&](int xs, int slot) {
        const int ic = xs / 9, rr = xs - ic * 9;
        const int kd = rr / 3, kh = rr - kd * 3;
        const __half* base = xT_n + (((size_t)(d + kd) * PH) + (h0 + kh)) * PW * C_ + ic * 64;
        const uint32_t dst = smem_u32(&XW[slot][0]);
#pragma unroll
        for (int it = 0; it < 4; ++it) {
            int cch = tid + it * 256;                 // 0..1023
            int row = cch >> 3, q = cch & 7;          // row = hh*66+ww in 0..127
            int hh = row / 66, ww = row - hh * 66;
            cp_async16(dst + (uint32_t)(row * LDT + q * 8) * 2,
                       base + ((size_t)hh * PW + ww) * C_ + q * 8);
        }
        if (tid < 32) {                               // chunks 1024..1055: rows 128..131
            int cch = 1024 + tid;
            int row = cch >> 3, q = cch & 7;
            int ww = row - 66;
            cp_async16(dst + (uint32_t)(row * LDT + q * 8) * 2,
                       base + ((size_t)1 * PW + ww) * C_ + q * 8);
        }
    };

    // W tile staging for substage u: t = (kd*3+kh)*3 + kw, i-chunk ic. 1024 chunks.
    auto stageW = [&](int u, int slot) {
        const int xs = u / 3, kw = u - xs * 3;
        const int ic = xs / 9, rr = xs - ic * 9;
        const int t = rr * 3 + kw;
        const __half* wb = wm_n + (size_t)t * C_ * C_ + ic * 64;
        const uint32_t dst = smem_u32(&WS[slot][0]);
#pragma unroll
        for (int it = 0; it < 4; ++it) {
            int cch = tid + it * 256;
            int row = cch >> 3, q = cch & 7;
            cp_async16(dst + (uint32_t)(row * LDT + q * 8) * 2,
                       wb + (size_t)row * C_ + q * 8);
        }
    };

    auto compute = [&](int kw, int xslot, int wslot) {
        const __half* Wbase = &WS[wslot][wo * 64 * LDT];
        const int z0 = wz * 32;
        const int hh0 = z0 >> 6, w00 = z0 & 63;
        const int z1 = z0 + 16;
        const int hh1 = z1 >> 6, w01 = z1 & 63;
        const __half* Xb0 = &XW[xslot][(hh0 * 66 + w00 + kw) * LDT];
        const __half* Xb1 = &XW[xslot][(hh1 * 66 + w01 + kw) * LDT];
#pragma unroll
        for (int k = 0; k < 4; ++k) {
            wmma::fragment<wmma::matrix_a, 16, 16, 16, __half, wmma::row_major> a[4];
            wmma::fragment<wmma::matrix_b, 16, 16, 16, __half, wmma::col_major> b[2];
            wmma::load_matrix_sync(b[0], Xb0 + k * 16, LDT);
            wmma::load_matrix_sync(b[1], Xb1 + k * 16, LDT);
#pragma unroll
            for (int m = 0; m < 4; ++m) {
                wmma::load_matrix_sync(a[m], Wbase + (m * 16) * LDT + k * 16, LDT);
#pragma unroll
                for (int nn = 0; nn < 2; ++nn)
                    wmma::mma_sync(c[m][nn], a[m], b[nn], c[m][nn]);
            }
        }
    };

    // Prologue: groups 0{X0,W0}, 1{W1}, 2{W2}. Substage u issues group u+3.
    stageX(0, 0); stageW(0, 0); CP_COMMIT();
    stageW(1, 1); CP_COMMIT();
    stageW(2, 2); CP_COMMIT();

    for (int u = 0; u < NSUB; ++u) {
        const int xs = u / 3, kw = u - xs * 3;
        if (u < NSUB - 3) CP_WAIT(2);
        else              CP_WAIT(0);
        __syncthreads();                 // data for substage u visible; old bufs free
        if (u + 3 < NSUB) {
            stageW(u + 3, (u + 3) & 3);
            if (kw == 0) stageX(xs + 1, (xs + 1) & 1);
            CP_COMMIT();
        }
        compute(kw, xs & 1, u & 3);
    }

    // Epilogue: 16x16 fragments straight to gmem (z tiles never straddle hh).
#pragma unroll
    for (int m = 0; m < 4; ++m) {
        const int o = wo * 64 + m * 16;
#pragma unroll
        for (int nn = 0; nn < 2; ++nn) {
            const int z = wz * 32 + nn * 16;
            const int hh = z >> 6, w0 = z & 63;
            float* dst = out + (((size_t)n * C_ + o) * D_ + d) * (H_ * W_) + (h0 + hh) * W_ + w0;
            wmma::store_matrix_sync(dst, c[m][nn], D_ * H_ * W_, wmma::mem_row_major);
        }
    }
}

// ---------------------------------------------------------------------------
extern "C" void kernel_launch(void* const* d_in, const int* in_sizes, int n_in,
                              void* d_out, int out_size) {
    const float* x      = (const float*)d_in[0];
    const float* latent = (const float*)d_in[1];
    const float* weight = (const float*)d_in[2];
    const float* fc_w   = (const float*)d_in[3];
    const float* fc_b   = (const float*)d_in[4];
    float* out = (float*)d_out;

    style_kernel<<<dim3(C_ / 4, N_), 128>>>(latent, fc_w, fc_b);
    prep_kernel<<<TBLOCKS + C_, 512>>>(x, weight);
    conv_kernel<<<dim3(H_ / 2, D_, N_), 256>>>(out);
}